// round 14
// baseline (speedup 1.0000x reference)
#include <cuda_runtime.h>
#include <math.h>
#include <stdint.h>

#define NB 4
#define NS 4096
#define ND 1024
#define NM (NB*NS)          // 16384 rows
#define NWIN 384
#define APR 128
#define LN_EPS 1e-6f
#define PADK 40             // 32 data + 8 pad: conflict-free LDS.64 phases

// Scratch (static device memory; no allocations anywhere).
__device__ float g_Q[(size_t)NM * ND];
__device__ float g_K[(size_t)NM * ND];
__device__ float g_V[(size_t)NM * ND];
__device__ float g_E[(size_t)NM * NWIN];
__device__ float g_XT[(size_t)NM * ND];        // tf32-rounded, k-permuted x
__device__ float g_WT[(size_t)5 * ND * ND];    // tf32-rounded, k-permuted weights

// ---------------------------------------------------------------------------
__device__ __forceinline__ float to_tf32(float x) {
    float r; asm("cvt.rna.tf32.f32 %0, %1;" : "=f"(r) : "f"(x)); return r;
}
__device__ __forceinline__ uint32_t fbits(float x) { return __float_as_uint(x); }
// K-permutation within 8-groups: natural k -> stored position.
// Stored order per group: [0,4,1,5,2,6,3,7]  (pairs (q, q+4) become adjacent)
__device__ __forceinline__ int kp(int k) {
    return (k & ~7) | (((k & 3) << 1) | ((k >> 2) & 1));
}
__device__ __forceinline__ uint32_t smem_u32(const void* p) {
    uint32_t a;
    asm("{ .reg .u64 t; cvta.to.shared.u64 t, %1; cvt.u32.u64 %0, t; }"
        : "=r"(a) : "l"(p));
    return a;
}
__device__ __forceinline__ void mma_tf32(float* c, const uint32_t* a, const uint32_t* b) {
    asm volatile(
        "mma.sync.aligned.m16n8k8.row.col.f32.tf32.tf32.f32 "
        "{%0,%1,%2,%3}, {%4,%5,%6,%7}, {%8,%9}, {%0,%1,%2,%3};"
        : "+f"(c[0]), "+f"(c[1]), "+f"(c[2]), "+f"(c[3])
        : "r"(a[0]), "r"(a[1]), "r"(a[2]), "r"(a[3]), "r"(b[0]), "r"(b[1]));
}
__device__ __forceinline__ void cp16(uint32_t dst, const void* src) {
    asm volatile("cp.async.cg.shared.global [%0], [%1], 16;"
                 :: "r"(dst), "l"(src) : "memory");
}
__device__ __forceinline__ void cp16z(uint32_t dst, const void* src, uint32_t nbytes) {
    asm volatile("cp.async.cg.shared.global [%0], [%1], 16, %2;"
                 :: "r"(dst), "l"(src), "r"(nbytes) : "memory");
}
__device__ __forceinline__ void cp_commit() {
    asm volatile("cp.async.commit_group;" ::: "memory");
}
__device__ __forceinline__ void cp_wait0() {
    asm volatile("cp.async.wait_group 0;" ::: "memory");
}

// One 128x128x32 chunk. SMEM tiles are k-PERMUTED: position k0+2*qc holds
// natural k0+qc, position k0+2*qc+1 holds natural k0+qc+4 -> LDS.64 frags.
__device__ __forceinline__ void mma_compute_chunk(
    const float* __restrict__ sa, const float* __restrict__ sb,
    float (&acc)[2][8][4], int wm, int wn, int qr, int qc)
{
#pragma unroll
    for (int ks = 0; ks < 4; ks++) {
        const int k0 = ks * 8;
        uint32_t af[2][4], bf[8][2];
#pragma unroll
        for (int mt = 0; mt < 2; mt++) {
            const float2 lo = *(const float2*)(sa + (wm + mt * 16 + qr) * PADK + k0 + 2 * qc);
            const float2 hi = *(const float2*)(sa + (wm + mt * 16 + qr + 8) * PADK + k0 + 2 * qc);
            af[mt][0] = fbits(lo.x); af[mt][2] = fbits(lo.y);
            af[mt][1] = fbits(hi.x); af[mt][3] = fbits(hi.y);
        }
#pragma unroll
        for (int nt = 0; nt < 8; nt++) {
            const float2 bb = *(const float2*)(sb + (wn + nt * 8 + qr) * PADK + k0 + 2 * qc);
            bf[nt][0] = fbits(bb.x); bf[nt][1] = fbits(bb.y);
        }
#pragma unroll
        for (int mt = 0; mt < 2; mt++)
#pragma unroll
            for (int nt = 0; nt < 8; nt++)
                mma_tf32(acc[mt][nt], af[mt], bf[nt]);
    }
}

// ---------------------------------------------------------------------------
// One-shot prep: tf32-round + k-permute x and the 5 GEMM weights.
// Block b < 16384 -> x (1024 floats each); else weights (1024 blocks each).
// ---------------------------------------------------------------------------
__global__ void __launch_bounds__(256)
round_perm_all(const float* __restrict__ x,
               const float* __restrict__ w0, const float* __restrict__ w1,
               const float* __restrict__ w2, const float* __restrict__ w3,
               const float* __restrict__ w4,
               float* __restrict__ XT, float* __restrict__ WT)
{
    const int bid = blockIdx.x;
    const float* src;
    float* dst;
    size_t off;
    if (bid < 16384) { src = x; dst = XT; off = (size_t)bid << 10; }
    else {
        const int wb = bid - 16384;
        const int wi = wb >> 10;
        if      (wi == 0) src = w0;
        else if (wi == 1) src = w1;
        else if (wi == 2) src = w2;
        else if (wi == 3) src = w3;
        else              src = w4;
        dst = WT + (size_t)wi * ND * ND;
        off = (size_t)(wb & 1023) << 10;
    }
    const size_t e0 = off + (size_t)threadIdx.x * 4;
    float4 v = *(const float4*)(src + e0);
    // positions: (e0 & ~7) + ((e0>>2)&1) + 2*i  for i = 0..3
    const size_t base = (e0 & ~(size_t)7) | ((e0 >> 2) & 1);
    dst[base + 0] = to_tf32(v.x);
    dst[base + 2] = to_tf32(v.y);
    dst[base + 4] = to_tf32(v.z);
    dst[base + 6] = to_tf32(v.w);
}

// ===========================================================================
// tf32 mma.sync TN GEMM, cp.async double-buffered; operands pre-permuted.
// EPI: 0 plain, 1 bias+relu, 2 +residual. ROUND: tf32-round output.
// PERM: write output k-permuted (when it feeds a GEMM along this dim).
// ===========================================================================
#define STG_FLOATS (128 * PADK)
#define GEMM2_SMEM (4 * STG_FLOATS * 4)

template<int EPI, int ROUND, int PERM>
__global__ void __launch_bounds__(256, 2)
mma_gemm2(const float* __restrict__ A, const float* __restrict__ W,
          const float* __restrict__ bias, const float* __restrict__ res,
          float* __restrict__ C)
{
    extern __shared__ float smem[];
    const uint32_t sb32 = smem_u32(smem);

    const int m0 = blockIdx.y << 7;
    const int n0 = blockIdx.x << 7;
    const int tid = threadIdx.x;
    const int w = tid >> 5, lane = tid & 31;
    const int wm = (w & 3) * 32, wn = (w >> 2) * 64;
    const int qr = lane >> 2, qc = lane & 3;

    float acc[2][8][4];
#pragma unroll
    for (int i = 0; i < 2; i++)
#pragma unroll
        for (int j = 0; j < 8; j++)
#pragma unroll
            for (int l = 0; l < 4; l++) acc[i][j][l] = 0.f;

    auto cp_chunk = [&](int t, int s) {
        const uint32_t dA = sb32 + (uint32_t)s * STG_FLOATS * 4;
        const uint32_t dB = sb32 + (uint32_t)(2 + s) * STG_FLOATS * 4;
        const float* Ab = A + (size_t)m0 * ND + t * 32;
        const float* Wb = W + (size_t)n0 * ND + t * 32;
#pragma unroll
        for (int i = 0; i < 4; i++) {
            const int idx = tid + i * 256;
            const int row = idx >> 3;
            const int seg = idx & 7;
            const uint32_t off = (uint32_t)(row * PADK + seg * 4) * 4;
            cp16(dA + off, Ab + (size_t)row * ND + seg * 4);
            cp16(dB + off, Wb + (size_t)row * ND + seg * 4);
        }
        cp_commit();
    };

    const int NT = ND / 32;
    cp_chunk(0, 0);
    for (int t = 0; t < NT; t++) {
        cp_wait0();
        __syncthreads();
        if (t + 1 < NT) cp_chunk(t + 1, (t + 1) & 1);
        const int s = t & 1;
        mma_compute_chunk(smem + s * STG_FLOATS, smem + (2 + s) * STG_FLOATS,
                          acc, wm, wn, qr, qc);
    }

    // Epilogue
#pragma unroll
    for (int mt = 0; mt < 2; mt++) {
        const int r0 = m0 + wm + mt * 16 + qr;
#pragma unroll
        for (int nt = 0; nt < 8; nt++) {
            const int col = n0 + wn + nt * 8 + qc * 2;
            float2 o0 = make_float2(acc[mt][nt][0], acc[mt][nt][1]);
            float2 o1 = make_float2(acc[mt][nt][2], acc[mt][nt][3]);
            if (EPI == 1) {
                const float b0 = bias[col], b1 = bias[col + 1];
                o0.x = fmaxf(o0.x + b0, 0.f); o0.y = fmaxf(o0.y + b1, 0.f);
                o1.x = fmaxf(o1.x + b0, 0.f); o1.y = fmaxf(o1.y + b1, 0.f);
            }
            if (EPI == 2) {
                const float2 r0v = *(const float2*)(res + (size_t)r0 * ND + col);
                const float2 r1v = *(const float2*)(res + (size_t)(r0 + 8) * ND + col);
                o0.x += r0v.x; o0.y += r0v.y;
                o1.x += r1v.x; o1.y += r1v.y;
            }
            if (ROUND) {
                o0.x = to_tf32(o0.x); o0.y = to_tf32(o0.y);
                o1.x = to_tf32(o1.x); o1.y = to_tf32(o1.y);
            }
            if (PERM) {
                const int p0 = kp(col), p1 = kp(col + 1);
                C[(size_t)r0 * ND + p0] = o0.x;
                C[(size_t)r0 * ND + p1] = o0.y;
                C[(size_t)(r0 + 8) * ND + p0] = o1.x;
                C[(size_t)(r0 + 8) * ND + p1] = o1.y;
            } else {
                *(float2*)(C + (size_t)r0 * ND + col) = o0;
                *(float2*)(C + (size_t)(r0 + 8) * ND + col) = o1;
            }
        }
    }
}

// ===========================================================================
// Banded scores: E = (Q . K^T)/32 over the 384 window (Q,K d-permuted).
// Output E natural (softmax consumes it with masking by natural j).
// ===========================================================================
__global__ void __launch_bounds__(256, 2)
mma_scores2(const float* __restrict__ Q, const float* __restrict__ Km,
            float* __restrict__ E)
{
    extern __shared__ float smem[];
    const uint32_t sb32 = smem_u32(smem);

    const int b  = blockIdx.z;
    const int i0 = blockIdx.y << 7;
    const int kt = blockIdx.x;
    const int tid = threadIdx.x;
    const int w = tid >> 5, lane = tid & 31;
    const int wm = (w & 3) * 32, wn = (w >> 2) * 64;
    const int qr = lane >> 2, qc = lane & 3;
    const int jbase = i0 - APR + kt * 128;

    float acc[2][8][4];
#pragma unroll
    for (int i = 0; i < 2; i++)
#pragma unroll
        for (int j = 0; j < 8; j++)
#pragma unroll
            for (int l = 0; l < 4; l++) acc[i][j][l] = 0.f;

    auto cp_chunk = [&](int t, int s) {
        const uint32_t dA = sb32 + (uint32_t)s * STG_FLOATS * 4;
        const uint32_t dB = sb32 + (uint32_t)(2 + s) * STG_FLOATS * 4;
        const float* Ab = Q + (size_t)(b * NS + i0) * ND + t * 32;
#pragma unroll
        for (int i = 0; i < 4; i++) {
            const int idx = tid + i * 256;
            const int row = idx >> 3;
            const int seg = idx & 7;
            const uint32_t off = (uint32_t)(row * PADK + seg * 4) * 4;
            cp16(dA + off, Ab + (size_t)row * ND + seg * 4);
            const int j = jbase + row;
            const bool ok = (j >= 0) && (j < NS);
            const int jc = ok ? j : 0;
            cp16z(dB + off, Km + (size_t)(b * NS + jc) * ND + t * 32 + seg * 4,
                  ok ? 16u : 0u);
        }
        cp_commit();
    };

    const int NT = ND / 32;
    cp_chunk(0, 0);
    for (int t = 0; t < NT; t++) {
        cp_wait0();
        __syncthreads();
        if (t + 1 < NT) cp_chunk(t + 1, (t + 1) & 1);
        const int s = t & 1;
        mma_compute_chunk(smem + s * STG_FLOATS, smem + (2 + s) * STG_FLOATS,
                          acc, wm, wn, qr, qc);
    }

    const float scale = 0.03125f;
#pragma unroll
    for (int mt = 0; mt < 2; mt++) {
        const int r0 = b * NS + i0 + wm + mt * 16 + qr;
#pragma unroll
        for (int nt = 0; nt < 8; nt++) {
            const int col = kt * 128 + wn + nt * 8 + qc * 2;
            *(float2*)(E + (size_t)r0 * NWIN + col) =
                make_float2(acc[mt][nt][0] * scale, acc[mt][nt][1] * scale);
            *(float2*)(E + (size_t)(r0 + 8) * NWIN + col) =
                make_float2(acc[mt][nt][2] * scale, acc[mt][nt][3] * scale);
        }
    }
}

// ===========================================================================
// Banded PV: alpha (l-permuted in gmem) x V (transpose permutes l in SMEM).
// Output c: tf32-rounded, d-PERMUTED (feeds Wo GEMM).
// ===========================================================================
#define PV_A_FLOATS (128 * PADK)
#define PV_VT_FLOATS (32 * 132)
#define PV_VT_OFF (2 * PV_A_FLOATS)
#define PV_B_OFF (PV_VT_OFF + 2 * PV_VT_FLOATS)
#define PV_SMEM ((PV_B_OFF + 128 * PADK) * 4)

__global__ void __launch_bounds__(256, 2)
pv_mma(const float* __restrict__ E, const float* __restrict__ V,
       float* __restrict__ C)
{
    extern __shared__ float smem[];
    const uint32_t sb32 = smem_u32(smem);

    const int b  = blockIdx.z;
    const int i0 = blockIdx.y << 7;
    const int d0 = blockIdx.x << 7;
    const int tid = threadIdx.x;
    const int w = tid >> 5, lane = tid & 31;
    const int wm = (w & 3) * 32, wn = (w >> 2) * 64;
    const int qr = lane >> 2, qc = lane & 3;
    const int jbase = i0 - APR;

    float acc[2][8][4];
#pragma unroll
    for (int i = 0; i < 2; i++)
#pragma unroll
        for (int j = 0; j < 8; j++)
#pragma unroll
            for (int l = 0; l < 4; l++) acc[i][j][l] = 0.f;

    auto cp_chunk = [&](int t, int s) {
        const uint32_t dA = sb32 + (uint32_t)s * PV_A_FLOATS * 4;
        const float* Ab = E + (size_t)(b * NS + i0) * NWIN + t * 32;
#pragma unroll
        for (int i = 0; i < 4; i++) {
            const int idx = tid + i * 256;
            const int row = idx >> 3;
            const int seg = idx & 7;
            cp16(dA + (uint32_t)(row * PADK + seg * 4) * 4,
                 Ab + (size_t)row * NWIN + seg * 4);
        }
        const uint32_t dV = sb32 + (uint32_t)(PV_VT_OFF + s * PV_VT_FLOATS) * 4;
#pragma unroll
        for (int i = 0; i < 4; i++) {
            const int idx = tid + i * 256;
            const int lrow = idx >> 5;
            const int dseg = idx & 31;
            const int j = jbase + t * 32 + lrow;
            const bool ok = (j >= 0) && (j < NS);
            const int jc = ok ? j : 0;
            cp16z(dV + (uint32_t)(lrow * 132 + dseg * 4) * 4,
                  V + (size_t)(b * NS + jc) * ND + d0 + dseg * 4,
                  ok ? 16u : 0u);
        }
        cp_commit();
    };

    const int NT = NWIN / 32;   // 12
    cp_chunk(0, 0);
    for (int t = 0; t < NT; t++) {
        cp_wait0();
        __syncthreads();
        // transpose sVt[t&1][l][d] -> sB[d][kp(l)]
        {
            const float* sv = smem + PV_VT_OFF + (t & 1) * PV_VT_FLOATS;
            float* sB = smem + PV_B_OFF;
            const int d = tid >> 1;
            const int l0 = (tid & 1) * 16;
#pragma unroll
            for (int s16 = 0; s16 < 16; s16++) {
                const int l = l0 + s16;
                sB[d * PADK + kp(l)] = sv[l * 132 + d];
            }
        }
        if (t + 1 < NT) cp_chunk(t + 1, (t + 1) & 1);
        __syncthreads();
        mma_compute_chunk(smem + (t & 1) * PV_A_FLOATS, smem + PV_B_OFF,
                          acc, wm, wn, qr, qc);
    }

    // Epilogue: tf32-round + d-permute (feeds Wo GEMM as A)
#pragma unroll
    for (int mt = 0; mt < 2; mt++) {
        const int r0 = b * NS + i0 + wm + mt * 16 + qr;
#pragma unroll
        for (int nt = 0; nt < 8; nt++) {
            const int col = d0 + wn + nt * 8 + qc * 2;
            const int p0 = kp(col), p1 = kp(col + 1);
            C[(size_t)r0 * ND + p0] = to_tf32(acc[mt][nt][0]);
            C[(size_t)r0 * ND + p1] = to_tf32(acc[mt][nt][1]);
            C[(size_t)(r0 + 8) * ND + p0] = to_tf32(acc[mt][nt][2]);
            C[(size_t)(r0 + 8) * ND + p1] = to_tf32(acc[mt][nt][3]);
        }
    }
}

// ===========================================================================
// Banded softmax; reads natural E, writes alpha tf32-rounded + l-PERMUTED.
// Safe in place: all reads precede all writes within the owning warp.
// ===========================================================================
__global__ void __launch_bounds__(256)
softmax_kernel(float* __restrict__ E)
{
    const int warp = threadIdx.x >> 5;
    const int lane = threadIdx.x & 31;
    const int r = blockIdx.x * 8 + warp;
    const int i = r & (NS - 1);
    const int i0 = i & ~127;
    const int jbase = i0 - APR;
    float* row = E + (size_t)r * NWIN;

    float vals[12];
    float mx = -INFINITY;
#pragma unroll
    for (int u = 0; u < 12; u++) {
        const int l = lane + 32 * u;
        const int j = jbase + l;
        const float e = row[l];
        const bool ok = (j >= 0) && (j < NS) && (j >= i - APR) && (j <= i + APR)
                        && (j != i) && (e != 0.0f);
        vals[u] = ok ? e : -INFINITY;
        mx = fmaxf(mx, vals[u]);
    }
#pragma unroll
    for (int o = 16; o; o >>= 1) mx = fmaxf(mx, __shfl_xor_sync(0xffffffffu, mx, o));

    float s = 0.f;
#pragma unroll
    for (int u = 0; u < 12; u++) {
        const float p = (vals[u] == -INFINITY) ? 0.f : expf(vals[u] - mx);
        vals[u] = p;
        s += p;
    }
#pragma unroll
    for (int o = 16; o; o >>= 1) s += __shfl_xor_sync(0xffffffffu, s, o);

    const float inv = 1.f / s;
#pragma unroll
    for (int u = 0; u < 12; u++) {
        const int l = lane + 32 * u;
        row[kp(l)] = to_tf32(vals[u] * inv);
    }
}

// ===========================================================================
// LayerNorm; PERM=1: tf32-round + k-permute output (feeds k1 GEMM).
// ===========================================================================
template<int PERM>
__global__ void __launch_bounds__(256)
ln_kernel(const float* __restrict__ In, const float* __restrict__ g,
          const float* __restrict__ bt, float* __restrict__ Y)
{
    const int r = blockIdx.x;
    const int tid = threadIdx.x;
    const float4 v = *(const float4*)(In + (size_t)r * ND + tid * 4);
    float s1 = v.x + v.y + v.z + v.w;
    float s2 = v.x*v.x + v.y*v.y + v.z*v.z + v.w*v.w;
    __shared__ float sh1[8], sh2[8];
    const int warp = tid >> 5, lane = tid & 31;
#pragma unroll
    for (int o = 16; o; o >>= 1) {
        s1 += __shfl_xor_sync(0xffffffffu, s1, o);
        s2 += __shfl_xor_sync(0xffffffffu, s2, o);
    }
    if (lane == 0) { sh1[warp] = s1; sh2[warp] = s2; }
    __syncthreads();
    float S1 = 0.f, S2 = 0.f;
#pragma unroll
    for (int w = 0; w < 8; w++) { S1 += sh1[w]; S2 += sh2[w]; }
    const float mu = S1 * (1.f / ND);
    const float var = S2 * (1.f / ND) - mu * mu;
    const float rstd = rsqrtf(var + LN_EPS);
    const float4 gg = *(const float4*)(g + tid * 4);
    const float4 bb = *(const float4*)(bt + tid * 4);
    float4 o;
    o.x = (v.x - mu) * rstd * gg.x + bb.x;
    o.y = (v.y - mu) * rstd * gg.y + bb.y;
    o.z = (v.z - mu) * rstd * gg.z + bb.z;
    o.w = (v.w - mu) * rstd * gg.w + bb.w;
    if (PERM) {
        const int d0v = tid * 4;
        const int base = (d0v & ~7) | ((d0v >> 2) & 1);
        float* Yr = Y + (size_t)r * ND;
        Yr[base + 0] = to_tf32(o.x);
        Yr[base + 2] = to_tf32(o.y);
        Yr[base + 4] = to_tf32(o.z);
        Yr[base + 6] = to_tf32(o.w);
    } else {
        *(float4*)(Y + (size_t)r * ND + tid * 4) = o;
    }
}

__global__ void __launch_bounds__(256)
ln_k2_kernel(const float* __restrict__ In, const float* __restrict__ g,
             const float* __restrict__ bt, const float* __restrict__ w2,
             const float* __restrict__ b2, float* __restrict__ Out)
{
    const int r = blockIdx.x;
    const int tid = threadIdx.x;
    const float4 v = *(const float4*)(In + (size_t)r * ND + tid * 4);
    float s1 = v.x + v.y + v.z + v.w;
    float s2 = v.x*v.x + v.y*v.y + v.z*v.z + v.w*v.w;
    __shared__ float sh1[8], sh2[8], sh3[8];
    const int warp = tid >> 5, lane = tid & 31;
#pragma unroll
    for (int o = 16; o; o >>= 1) {
        s1 += __shfl_xor_sync(0xffffffffu, s1, o);
        s2 += __shfl_xor_sync(0xffffffffu, s2, o);
    }
    if (lane == 0) { sh1[warp] = s1; sh2[warp] = s2; }
    __syncthreads();
    float S1 = 0.f, S2 = 0.f;
#pragma unroll
    for (int w = 0; w < 8; w++) { S1 += sh1[w]; S2 += sh2[w]; }
    const float mu = S1 * (1.f / ND);
    const float var = S2 * (1.f / ND) - mu * mu;
    const float rstd = rsqrtf(var + LN_EPS);
    const float4 gg = *(const float4*)(g + tid * 4);
    const float4 bb = *(const float4*)(bt + tid * 4);
    const float4 ww = *(const float4*)(w2 + tid * 4);
    float d = ((v.x - mu) * rstd * gg.x + bb.x) * ww.x
            + ((v.y - mu) * rstd * gg.y + bb.y) * ww.y
            + ((v.z - mu) * rstd * gg.z + bb.z) * ww.z
            + ((v.w - mu) * rstd * gg.w + bb.w) * ww.w;
#pragma unroll
    for (int o = 16; o; o >>= 1) d += __shfl_xor_sync(0xffffffffu, d, o);
    if (lane == 0) sh3[warp] = d;
    __syncthreads();
    if (tid == 0) {
        float D2 = 0.f;
#pragma unroll
        for (int w = 0; w < 8; w++) D2 += sh3[w];
        Out[r] = 1.f / (1.f + expf(-(D2 + b2[0])));
    }
}

// ===========================================================================
extern "C" void kernel_launch(void* const* d_in, const int* in_sizes, int n_in,
                              void* d_out, int out_size)
{
    const float* x   = (const float*)d_in[0];
    const float* Wq  = (const float*)d_in[1];
    const float* Wk  = (const float*)d_in[2];
    const float* Wv  = (const float*)d_in[3];
    const float* Wo  = (const float*)d_in[4];
    const float* k1w = (const float*)d_in[5];
    const float* k1b = (const float*)d_in[6];
    const float* k2w = (const float*)d_in[7];
    const float* k2b = (const float*)d_in[8];
    const float* lng = (const float*)d_in[9];
    const float* lnb = (const float*)d_in[10];
    float* out = (float*)d_out;

    float *Qd, *Kd, *Vd, *Ed, *XT, *WT;
    cudaGetSymbolAddress((void**)&Qd, g_Q);
    cudaGetSymbolAddress((void**)&Kd, g_K);
    cudaGetSymbolAddress((void**)&Vd, g_V);
    cudaGetSymbolAddress((void**)&Ed, g_E);
    cudaGetSymbolAddress((void**)&XT, g_XT);
    cudaGetSymbolAddress((void**)&WT, g_WT);

    cudaFuncSetAttribute(mma_gemm2<0,1,1>, cudaFuncAttributeMaxDynamicSharedMemorySize, GEMM2_SMEM);
    cudaFuncSetAttribute(mma_gemm2<0,1,0>, cudaFuncAttributeMaxDynamicSharedMemorySize, GEMM2_SMEM);
    cudaFuncSetAttribute(mma_gemm2<2,0,0>, cudaFuncAttributeMaxDynamicSharedMemorySize, GEMM2_SMEM);
    cudaFuncSetAttribute(mma_gemm2<1,0,0>, cudaFuncAttributeMaxDynamicSharedMemorySize, GEMM2_SMEM);
    cudaFuncSetAttribute(mma_scores2,      cudaFuncAttributeMaxDynamicSharedMemorySize, GEMM2_SMEM);
    cudaFuncSetAttribute(pv_mma,           cudaFuncAttributeMaxDynamicSharedMemorySize, PV_SMEM);

    // Prep: tf32-round + k-permute GEMM operands (one fused launch).
    round_perm_all<<<16384 + 5 * 1024, 256>>>(x, Wq, Wk, Wv, Wo, k1w, XT, WT);

    const dim3 gw(ND / 128, NM / 128);   // (8, 128)
    // Q, K: d-permuted (feed scores along d). V: natural d (pv's n-dim).
    mma_gemm2<0,1,1><<<gw, 256, GEMM2_SMEM>>>(XT, WT + 0*(size_t)ND*ND, nullptr, nullptr, Qd);
    mma_gemm2<0,1,1><<<gw, 256, GEMM2_SMEM>>>(XT, WT + 1*(size_t)ND*ND, nullptr, nullptr, Kd);
    mma_gemm2<0,1,0><<<gw, 256, GEMM2_SMEM>>>(XT, WT + 2*(size_t)ND*ND, nullptr, nullptr, Vd);

    mma_scores2<<<dim3(3, NS / 128, NB), 256, GEMM2_SMEM>>>(Qd, Kd, Ed);
    softmax_kernel<<<NM / 8, 256>>>(Ed);
    pv_mma<<<dim3(ND / 128, NS / 128, NB), 256, PV_SMEM>>>(Ed, Vd, Qd);   // c -> g_Q

    mma_gemm2<2,0,0><<<gw, 256, GEMM2_SMEM>>>(Qd, WT + 3*(size_t)ND*ND, nullptr, x, Kd);
    ln_kernel<1><<<NM, 256>>>(Kd, lng, lnb, Vd);                          // y -> g_V (permuted)
    mma_gemm2<1,0,0><<<gw, 256, GEMM2_SMEM>>>(Vd, WT + 4*(size_t)ND*ND, k1b, nullptr, Qd);
    ln_k2_kernel<<<NM, 256>>>(Qd, lng, lnb, k2w, k2b, out);
}